// round 15
// baseline (speedup 1.0000x reference)
#include <cuda_runtime.h>
#include <cuda_bf16.h>
#include <cstdint>
#include <string.h>
#include <math.h>

#define NSWEEP 5
#define FULL 0xffffffffu

typedef unsigned long long u64;

// scratch: Y matrices (4096 x 20 x 20) + ready flags
__device__ float g_Y[4096 * 400];
__device__ int g_flag[4096];   // zero-init; stale '1' across replays is benign (Y deterministic)

// ---------------------------------------------------------------------------
// helpers
// ---------------------------------------------------------------------------
__device__ __forceinline__ uint32_t s2u(const void* p) {
  return (uint32_t)__cvta_generic_to_shared(p);
}
__device__ __forceinline__ void ldsm4(uint32_t addr, uint32_t* r) {
  asm volatile("ldmatrix.sync.aligned.m8n8.x4.shared.b16 {%0,%1,%2,%3}, [%4];"
               : "=r"(r[0]), "=r"(r[1]), "=r"(r[2]), "=r"(r[3]) : "r"(addr));
}
__device__ __forceinline__ void mma16816(float* d, const uint32_t* a,
                                         uint32_t b0, uint32_t b1) {
  asm volatile(
      "mma.sync.aligned.m16n8k16.row.col.f32.bf16.bf16.f32 "
      "{%0,%1,%2,%3},{%4,%5,%6,%7},{%8,%9},{%0,%1,%2,%3};"
      : "+f"(d[0]), "+f"(d[1]), "+f"(d[2]), "+f"(d[3])
      : "r"(a[0]), "r"(a[1]), "r"(a[2]), "r"(a[3]), "r"(b0), "r"(b1));
}
__device__ __forceinline__ void bsplit(float v, __nv_bfloat16& h, __nv_bfloat16& l) {
  h = __float2bfloat16(v);
  l = __float2bfloat16(v - __bfloat162float(h));
}
__device__ __forceinline__ uint32_t b2u(__nv_bfloat162 v) {
  uint32_t r; memcpy(&r, &v, 4); return r;
}
__device__ __forceinline__ u64 mk64(uint32_t lo, uint32_t hi) {
  return (u64)lo | ((u64)hi << 32);
}

// ---- packed f32x2 helpers ----
__device__ __forceinline__ u64 pk2(float lo, float hi) {
  u64 r; asm("mov.b64 %0,{%1,%2};" : "=l"(r) : "f"(lo), "f"(hi)); return r;
}
__device__ __forceinline__ u64 bc2(float v) { return pk2(v, v); }
__device__ __forceinline__ void up2(u64 v, float& lo, float& hi) {
  asm("mov.b64 {%0,%1},%2;" : "=f"(lo), "=f"(hi) : "l"(v));
}
__device__ __forceinline__ u64 fma2(u64 a, u64 b, u64 c) {
  u64 d; asm("fma.rn.f32x2 %0,%1,%2,%3;" : "=l"(d) : "l"(a), "l"(b), "l"(c)); return d;
}
__device__ __forceinline__ u64 mul2(u64 a, u64 b) {
  u64 d; asm("mul.rn.f32x2 %0,%1,%2;" : "=l"(d) : "l"(a), "l"(b)); return d;
}
__device__ __forceinline__ u64 add2(u64 a, u64 b) {
  u64 d; asm("add.rn.f32x2 %0,%1,%2;" : "=l"(d) : "l"(a), "l"(b)); return d;
}
__device__ __forceinline__ u64 neg2(u64 a) { return a ^ 0x8000000080000000ULL; }

__device__ __forceinline__ int ld_acq(const int* p) {
  int v; asm volatile("ld.acquire.gpu.global.u32 %0,[%1];" : "=r"(v) : "l"(p)); return v;
}

// gram smem byte layout (total 93696):
#define OFF_XL  33792
#define OFF_KK  67584
#define OFF_WTH 84224
#define OFF_WTL 88832
#define OFF_SQ  93440
#define SMEM_BYTES 93696

// ---------------------------------------------------------------------------
// gram body: centering + tensor-core Gram + exp + tensor-core P=KW, Y=W^T P
// 256 threads; publishes g_flag[b] when Y[b] is complete.
// ---------------------------------------------------------------------------
__device__ void gram_body(const float* __restrict__ x, const float* __restrict__ W,
                          char* smc, int b) {
  __nv_bfloat16* Xh = (__nv_bfloat16*)smc;              // 64 x 264
  __nv_bfloat16* Xl = (__nv_bfloat16*)(smc + OFF_XL);   // 64 x 264
  float* KK  = (float*)(smc + OFF_KK);                  // 64 x 65
  __nv_bfloat16* Wth = (__nv_bfloat16*)(smc + OFF_WTH); // 32 x 72
  __nv_bfloat16* Wtl = (__nv_bfloat16*)(smc + OFF_WTL);
  float* sq  = (float*)(smc + OFF_SQ);                  // 64
  __nv_bfloat16* Kh  = (__nv_bfloat16*)smc;             // 64 x 72
  __nv_bfloat16* Kl  = (__nv_bfloat16*)(smc + 9216);    // 64 x 72
  __nv_bfloat16* Pth = (__nv_bfloat16*)(smc + OFF_XL);          // 32 x 72
  __nv_bfloat16* Ptl = (__nv_bfloat16*)(smc + OFF_XL + 4608);   // 32 x 72

  const int tid  = threadIdx.x;
  const int warp = tid >> 5;
  const int lane = tid & 31;

  for (int i = tid; i < 20 * 64; i += 256) {
    const int d = i >> 6, k = i & 63;
    const float w = W[k * 20 + d];
    __nv_bfloat16 h, l;
    bsplit(w, h, l);
    Wth[d * 72 + k] = h;
    Wtl[d * 72 + k] = l;
  }

  const float* xb = x + (size_t)b * (64 * 256);
#pragma unroll
  for (int r8 = 0; r8 < 8; r8++) {
    const int r = warp * 8 + r8;
    const float4* row = (const float4*)(xb + r * 256);
    float4 v0 = row[lane];
    float4 v1 = row[lane + 32];
    float s = v0.x + v0.y + v0.z + v0.w + v1.x + v1.y + v1.z + v1.w;
    s += __shfl_xor_sync(FULL, s, 16);
    s += __shfl_xor_sync(FULL, s, 8);
    s += __shfl_xor_sync(FULL, s, 4);
    s += __shfl_xor_sync(FULL, s, 2);
    s += __shfl_xor_sync(FULL, s, 1);
    const float m = s * (1.0f / 256.0f);
    v0.x -= m; v0.y -= m; v0.z -= m; v0.w -= m;
    v1.x -= m; v1.y -= m; v1.z -= m; v1.w -= m;

    u64* ph0 = (u64*)(Xh + r * 264 + 4 * lane);
    u64* pl0 = (u64*)(Xl + r * 264 + 4 * lane);
    u64* ph1 = (u64*)(Xh + r * 264 + 128 + 4 * lane);
    u64* pl1 = (u64*)(Xl + r * 264 + 128 + 4 * lane);

    __nv_bfloat16 h0, l0, h1, l1, h2, l2, h3, l3;
    bsplit(v0.x, h0, l0); bsplit(v0.y, h1, l1);
    bsplit(v0.z, h2, l2); bsplit(v0.w, h3, l3);
    ph0[0] = mk64(b2u(__nv_bfloat162(h0, h1)), b2u(__nv_bfloat162(h2, h3)));
    pl0[0] = mk64(b2u(__nv_bfloat162(l0, l1)), b2u(__nv_bfloat162(l2, l3)));
    bsplit(v1.x, h0, l0); bsplit(v1.y, h1, l1);
    bsplit(v1.z, h2, l2); bsplit(v1.w, h3, l3);
    ph1[0] = mk64(b2u(__nv_bfloat162(h0, h1)), b2u(__nv_bfloat162(h2, h3)));
    pl1[0] = mk64(b2u(__nv_bfloat162(l0, l1)), b2u(__nv_bfloat162(l2, l3)));
  }
  __syncthreads();

  const int mrow = lane & 7;
  const int msel = lane >> 3;
  const int cofs = (msel >> 1) * 8;
  const int rsel = (msel & 1) * 8;
  const int r0 = lane >> 2;
  const int cb = 2 * (lane & 3);

  {
    const int bj = (warp & 3) * 16;
    const int bi = (warp >> 2) * 16;
    const uint32_t LOFF = 64 * 264 * 2;

    uint32_t aA0 = s2u(Xh + (bi + rsel + mrow) * 264 + cofs);
    uint32_t aA1 = aA0 + 32 * 264 * 2;
    uint32_t aB  = s2u(Xh + (bj + rsel + mrow) * 264 + cofs);

    float c0[8], c1[8];
#pragma unroll
    for (int i = 0; i < 8; i++) { c0[i] = 0.f; c1[i] = 0.f; }

#pragma unroll 4
    for (int kc = 0; kc < 16; kc++) {
      uint32_t Ah[4], Al[4], Bh[4], Bl[4], A1h[4], A1l[4];
      ldsm4(aA0, Ah);  ldsm4(aA0 + LOFF, Al);
      ldsm4(aA1, A1h); ldsm4(aA1 + LOFF, A1l);
      ldsm4(aB, Bh);   ldsm4(aB + LOFF, Bl);

      mma16816(c0,     Ah,  Bh[0], Bh[2]);
      mma16816(c0,     Ah,  Bl[0], Bl[2]);
      mma16816(c0,     Al,  Bh[0], Bh[2]);
      mma16816(c0 + 4, Ah,  Bh[1], Bh[3]);
      mma16816(c0 + 4, Ah,  Bl[1], Bl[3]);
      mma16816(c0 + 4, Al,  Bh[1], Bh[3]);

      mma16816(c1,     A1h, Bh[0], Bh[2]);
      mma16816(c1,     A1h, Bl[0], Bl[2]);
      mma16816(c1,     A1l, Bh[0], Bh[2]);
      mma16816(c1 + 4, A1h, Bh[1], Bh[3]);
      mma16816(c1 + 4, A1h, Bl[1], Bl[3]);
      mma16816(c1 + 4, A1l, Bh[1], Bh[3]);

      aA0 += 32; aA1 += 32; aB += 32;
    }

    float* K0 = KK + (bi + r0) * 65 + bj + cb;
    K0[0] = c0[0];  K0[1] = c0[1];
    K0[8 * 65] = c0[2];  K0[8 * 65 + 1] = c0[3];
    K0[8] = c0[4];  K0[9] = c0[5];
    K0[8 * 65 + 8] = c0[6];  K0[8 * 65 + 9] = c0[7];
    float* K1 = KK + (bi + 32 + r0) * 65 + bj + cb;
    K1[0] = c1[0];  K1[1] = c1[1];
    K1[8 * 65] = c1[2];  K1[8 * 65 + 1] = c1[3];
    K1[8] = c1[4];  K1[9] = c1[5];
    K1[8 * 65 + 8] = c1[6];  K1[8 * 65 + 9] = c1[7];
  }
  __syncthreads();

  if (tid < 64) sq[tid] = KK[tid * 65 + tid];
  __syncthreads();

  for (int e = tid; e < 4096; e += 256) {
    const int c = e >> 6, d = e & 63;
    const float g = KK[c * 65 + d];
    float d2 = sq[c] + sq[d] - 2.f * g;
    d2 = fmaxf(d2, 0.f) * (1.0f / 256.0f);
    const float kv = __expf(-50.f * d2);
    __nv_bfloat16 h, l;
    bsplit(kv, h, l);
    Kh[c * 72 + d] = h;
    Kl[c * 72 + d] = l;
  }
  __syncthreads();

  {
    const int bi = (warp & 3) * 16;
    const int nh = (warp >> 2) * 16;

    uint32_t aA = s2u(Kh + (bi + rsel + mrow) * 72 + cofs);
    uint32_t aB = s2u(Wth + (nh + rsel + mrow) * 72 + cofs);
    const uint32_t KLO = 9216;
    const uint32_t WLO = 4608;

    float c0[8];
#pragma unroll
    for (int i = 0; i < 8; i++) c0[i] = 0.f;

#pragma unroll
    for (int kc = 0; kc < 4; kc++) {
      uint32_t Ah[4], Al[4], Bh[4], Bl[4];
      ldsm4(aA, Ah); ldsm4(aA + KLO, Al);
      ldsm4(aB, Bh); ldsm4(aB + WLO, Bl);
      mma16816(c0,     Ah, Bh[0], Bh[2]);
      mma16816(c0,     Ah, Bl[0], Bl[2]);
      mma16816(c0,     Al, Bh[0], Bh[2]);
      mma16816(c0 + 4, Ah, Bh[1], Bh[3]);
      mma16816(c0 + 4, Ah, Bl[1], Bl[3]);
      mma16816(c0 + 4, Al, Bh[1], Bh[3]);
      aA += 32; aB += 32;
    }

    const int cc0 = bi + r0;
    const int cc1 = bi + r0 + 8;
    const int dd0 = nh + cb;
    __nv_bfloat16 h, l;
#pragma unroll
    for (int i = 0; i < 8; i++) {
      const int dd = dd0 + (i & 1) + ((i >> 2) << 3);
      const int cc = (i & 2) ? cc1 : cc0;
      bsplit(c0[i], h, l);
      Pth[dd * 72 + cc] = h;
      Ptl[dd * 72 + cc] = l;
    }
  }
  __syncthreads();

  if (warp < 4) {
    const int e0 = (warp & 1) * 16;
    const int f0 = (warp >> 1) * 16;

    uint32_t aA = s2u(Wth + (e0 + rsel + mrow) * 72 + cofs);
    uint32_t aB = s2u(Pth + (f0 + rsel + mrow) * 72 + cofs);
    const uint32_t WLO = 4608;
    const uint32_t PLO = 4608;

    float c0[8];
#pragma unroll
    for (int i = 0; i < 8; i++) c0[i] = 0.f;

#pragma unroll
    for (int kc = 0; kc < 4; kc++) {
      uint32_t Ah[4], Al[4], Bh[4], Bl[4];
      ldsm4(aA, Ah); ldsm4(aA + WLO, Al);
      ldsm4(aB, Bh); ldsm4(aB + PLO, Bl);
      mma16816(c0,     Ah, Bh[0], Bh[2]);
      mma16816(c0,     Ah, Bl[0], Bl[2]);
      mma16816(c0,     Al, Bh[0], Bh[2]);
      mma16816(c0 + 4, Ah, Bh[1], Bh[3]);
      mma16816(c0 + 4, Ah, Bl[1], Bl[3]);
      mma16816(c0 + 4, Al, Bh[1], Bh[3]);
      aA += 32; aB += 32;
    }

    float* Yb = g_Y + (size_t)b * 400;
#pragma unroll
    for (int i = 0; i < 8; i++) {
      const int ee = e0 + r0 + ((i & 2) ? 8 : 0);
      const int ff = f0 + cb + (i & 1) + ((i >> 2) << 3);
      if (ee < 20 && ff < 20) Yb[ee * 20 + ff] = c0[i];
    }
  }

  // publish readiness
  __syncthreads();
  if (tid == 0) {
    __threadfence();
    atomicExch(&g_flag[b], 1);
  }
}

// ---------------------------------------------------------------------------
// eig body: packed-f32x2 warp Jacobi, smem exchange, 8 warps x 2 matrices.
// Per-warp smem region (6720 B) inside dynamic smem.
// ---------------------------------------------------------------------------
__device__ void eig_body(const float* __restrict__ lin_w,
                         const float* __restrict__ lin_b,
                         float* __restrict__ out, char* smc, int g) {
  const int warp = threadIdx.x >> 5;
  const int lane = threadIdx.x & 31;
  char* wsm = smc + warp * 6720;
  ulonglong2* rowbuf = (ulonglong2*)(wsm);            // [10][33]
  u64*        dgbuf  = (u64*)(wsm + 5280);            // [32]
  ulonglong2* csbuf  = (ulonglong2*)(wsm + 5536);     // [20]

  const int b0 = g * 16 + warp * 2;

  // wait for both producers
  if (lane == 0) {
    while (true) {
      const int f0 = ld_acq(g_flag + b0);
      const int f1 = ld_acq(g_flag + b0 + 1);
      if (f0 && f1) break;
      __nanosleep(256);
    }
  }
  __syncwarp();

  const float* Y0 = g_Y + (size_t)b0 * 400;
  const float* Y1 = Y0 + 400;

  u64 a[20], u[20];
#pragma unroll
  for (int j = 0; j < 20; j++) {
    a[j] = (lane < 20) ? pk2(Y0[lane * 20 + j], Y1[lane * 20 + j]) : 0ULL;
    u[j] = (lane == j) ? bc2(1.f) : 0ULL;
  }
  u64 dg = (lane < 20) ? pk2(Y0[lane * 21], Y1[lane * 21]) : 0ULL;

  int m = (lane + 37) % 19;

  for (int sw = 0; sw < NSWEEP; sw++) {
#pragma unroll
    for (int r = 0; r < 19; r++) {
      const int C = (2 * r + 18) % 19;
      const int D = ((18 + r) % 19) + 1;
      int uu = C - lane;
      uu += (uu < 0) ? 19 : 0;
      uu += (uu < 0) ? 19 : 0;
      int t = (m == 18) ? 0 : uu + 1;
      t = (lane == 0) ? D : t;
      const bool isp = lane < t;
      const bool act = lane < 20;

      // ---- publish pre-round rows + diagonal (active lanes only) ----
      if (act) {
#pragma unroll
        for (int mm = 0; mm < 10; mm++) {
          ulonglong2 v; v.x = a[2 * mm]; v.y = a[2 * mm + 1];
          rowbuf[mm * 33 + lane] = v;
        }
        dgbuf[lane] = dg;
      }
      __syncwarp();

      // ---- gather: apq (symmetrized) and partner diagonal ----
      u64 apq = bc2(1.f), att = 0ULL;
      if (act) {
        const ulonglong2 own_pair = rowbuf[(t >> 1) * 33 + lane];
        const u64 apq_own = (t & 1) ? own_pair.y : own_pair.x;
        const ulonglong2 oth_pair = rowbuf[(lane >> 1) * 33 + t];
        const u64 apq_oth = (lane & 1) ? oth_pair.y : oth_pair.x;
        apq = mul2(bc2(0.5f), add2(apq_own, apq_oth));
        att = dgbuf[t];
      }

      // ---- angles (identical bits on both pair lanes) ----
      float apqx, apqy, dgx, dgy, atx, aty;
      up2(apq, apqx, apqy);
      up2(dg, dgx, dgy);
      up2(att, atx, aty);
      float cx, sx, tgx, cy, sy, tgy;
      {
        const float app = isp ? dgx : atx;
        const float aqq = isp ? atx : dgx;
        const float tau = (aqq - app) * (0.5f / apqx);
        const float tt  = copysignf(1.f, tau) / (fabsf(tau) + sqrtf(fmaf(tau, tau, 1.f)));
        const float cc  = rsqrtf(fmaf(tt, tt, 1.f));
        const bool ok = (fabsf(apqx) > 1e-20f) && act;
        cx  = ok ? cc : 1.f;
        sx  = ok ? tt * cc : 0.f;
        tgx = ok ? tt : 0.f;
      }
      {
        const float app = isp ? dgy : aty;
        const float aqq = isp ? aty : dgy;
        const float tau = (aqq - app) * (0.5f / apqy);
        const float tt  = copysignf(1.f, tau) / (fabsf(tau) + sqrtf(fmaf(tau, tau, 1.f)));
        const float cc  = rsqrtf(fmaf(tt, tt, 1.f));
        const bool ok = (fabsf(apqy) > 1e-20f) && act;
        cy  = ok ? cc : 1.f;
        sy  = ok ? tt * cc : 0.f;
        tgy = ok ? tt : 0.f;
      }
      const u64 c  = pk2(cx, cy);
      const u64 s  = pk2(sx, sy);
      const u64 tg = pk2(tgx, tgy);

      dg = fma2(isp ? neg2(tg) : tg, apq, dg);

      // ---- pair leader publishes (c,s) for col phase ----
      if (isp) { ulonglong2 cs; cs.x = c; cs.y = s; csbuf[lane] = cs; }

      // ---- row phase (active lanes only) ----
      if (act) {
        const u64 se = isp ? neg2(s) : s;
#pragma unroll
        for (int mm = 0; mm < 10; mm++) {
          const ulonglong2 rt = rowbuf[mm * 33 + t];
          a[2 * mm]     = fma2(se, rt.x, mul2(c, a[2 * mm]));
          a[2 * mm + 1] = fma2(se, rt.y, mul2(c, a[2 * mm + 1]));
        }
      }
      __syncwarp();

      // ---- col phase: broadcast (c,s) reads at compile-time slots ----
#pragma unroll
      for (int k = 0; k < 10; k++) {
        const int u0 = (k == 0) ? 0 : ((k - 1 + r) % 19) + 1;
        const int v0 = ((18 - k + r) % 19) + 1;
        const int pk = u0 < v0 ? u0 : v0;
        const int qk = u0 < v0 ? v0 : u0;
        const ulonglong2 cs = csbuf[pk];
        const u64 ck  = cs.x;
        const u64 sk  = cs.y;
        const u64 nsk = neg2(sk);
        const u64 ap = a[pk], aq = a[qk];
        a[pk] = fma2(nsk, aq, mul2(ck, ap));
        a[qk] = fma2(sk,  ap, mul2(ck, aq));
        const u64 up = u[pk], uq = u[qk];
        u[pk] = fma2(nsk, uq, mul2(ck, up));
        u[qk] = fma2(sk,  up, mul2(ck, uq));
      }

      m = (m == 0) ? 18 : m - 1;
    }
  }

  // ---- eigenvalues from converged diagonal of a[] ----
  u64 lam = 0ULL;
#pragma unroll
  for (int j = 0; j < 20; j++) lam = (lane == j) ? a[j] : lam;
  float lamx, lamy;
  up2(lam, lamx, lamy);
  const u64 lg_pk = pk2(__logf(fmaxf(lamx, 1e-4f)), __logf(fmaxf(lamy, 1e-4f)));

  // ---- overlay tail buffers on Jacobi buffers ----
  __syncwarp();
  u64* sW = (u64*)(wsm);           // [420] 20x21 packed
  u64* sU = (u64*)(wsm + 3360);    // [420]

#pragma unroll
  for (int j = 0; j < 20; j++) {
    const u64 lgj = __shfl_sync(FULL, lg_pk, j);
    if (lane < 20) {
      sW[lane * 21 + j] = mul2(u[j], lgj);
      sU[lane * 21 + j] = u[j];
    }
  }
  __syncwarp();

  u64 accv[10];
#pragma unroll
  for (int h = 0; h < 10; h++) accv[h] = 0ULL;

  for (int t = lane; t < 210; t += 32) {
    int i = (int)((41.0f - sqrtf(fmaf(-8.f, (float)t, 1681.0f))) * 0.5f);
    int st = 20 * i - ((i * (i - 1)) >> 1);
    if (st > t) { i--; st = 20 * i - ((i * (i - 1)) >> 1); }
    else if (t >= st + (20 - i)) { st += 20 - i; i++; }
    const int k = i + (t - st);
    u64 mm = 0ULL;
#pragma unroll
    for (int j = 0; j < 20; j++)
      mm = fma2(sW[i * 21 + j], sU[k * 21 + j], mm);
#pragma unroll
    for (int h = 0; h < 10; h++)
      accv[h] = fma2(mm, bc2(lin_w[h * 210 + t]), accv[h]);
  }
#pragma unroll
  for (int h = 0; h < 10; h++) {
    u64 v = accv[h];
    v = add2(v, __shfl_xor_sync(FULL, v, 16));
    v = add2(v, __shfl_xor_sync(FULL, v, 8));
    v = add2(v, __shfl_xor_sync(FULL, v, 4));
    v = add2(v, __shfl_xor_sync(FULL, v, 2));
    v = add2(v, __shfl_xor_sync(FULL, v, 1));
    accv[h] = v;
  }
  if (lane == 0) {
#pragma unroll
    for (int h = 0; h < 10; h++) {
      float vx, vy;
      up2(accv[h], vx, vy);
      const float bb = lin_b[h];
      out[b0 * 10 + h]      = vx + bb;
      out[b0 * 10 + 10 + h] = vy + bb;
    }
  }
}

// ---------------------------------------------------------------------------
// fused kernel: interleaved gram / eig blocks. 17-block groups: 16 gram
// producers immediately followed by the eig consumer of those 16 batches.
// ---------------------------------------------------------------------------
__global__ __launch_bounds__(256, 2) void fused_kernel(const float* __restrict__ x,
                                                       const float* __restrict__ W,
                                                       const float* __restrict__ lw,
                                                       const float* __restrict__ lb,
                                                       float* __restrict__ out) {
  extern __shared__ char smc[];
  const int idx = blockIdx.x;
  const int g = idx / 17;
  const int r = idx - g * 17;
  if (r < 16) {
    gram_body(x, W, smc, g * 16 + r);
  } else {
    eig_body(lw, lb, out, smc, g);
  }
}

// ---------------------------------------------------------------------------
extern "C" void kernel_launch(void* const* d_in, const int* in_sizes, int n_in,
                              void* d_out, int out_size) {
  const float* x  = (const float*)d_in[0];
  const float* W  = (const float*)d_in[1];
  const float* lw = (const float*)d_in[2];
  const float* lb = (const float*)d_in[3];
  float* out = (float*)d_out;

  cudaFuncSetAttribute(fused_kernel, cudaFuncAttributeMaxDynamicSharedMemorySize,
                       SMEM_BYTES);

  fused_kernel<<<4352, 256, SMEM_BYTES>>>(x, W, lw, lb, out);
}

// round 16
// speedup vs baseline: 1.1965x; 1.1965x over previous
#include <cuda_runtime.h>
#include <cuda_bf16.h>
#include <cstdint>
#include <string.h>
#include <math.h>

#define NSWEEP 5
#define FULL 0xffffffffu

typedef unsigned long long u64;

// scratch: Y matrices (4096 x 20 x 20)
__device__ float g_Y[4096 * 400];

// ---------------------------------------------------------------------------
// helpers
// ---------------------------------------------------------------------------
__device__ __forceinline__ uint32_t s2u(const void* p) {
  return (uint32_t)__cvta_generic_to_shared(p);
}
__device__ __forceinline__ void ldsm4(uint32_t addr, uint32_t* r) {
  asm volatile("ldmatrix.sync.aligned.m8n8.x4.shared.b16 {%0,%1,%2,%3}, [%4];"
               : "=r"(r[0]), "=r"(r[1]), "=r"(r[2]), "=r"(r[3]) : "r"(addr));
}
__device__ __forceinline__ void mma16816(float* d, const uint32_t* a,
                                         uint32_t b0, uint32_t b1) {
  asm volatile(
      "mma.sync.aligned.m16n8k16.row.col.f32.bf16.bf16.f32 "
      "{%0,%1,%2,%3},{%4,%5,%6,%7},{%8,%9},{%0,%1,%2,%3};"
      : "+f"(d[0]), "+f"(d[1]), "+f"(d[2]), "+f"(d[3])
      : "r"(a[0]), "r"(a[1]), "r"(a[2]), "r"(a[3]), "r"(b0), "r"(b1));
}
__device__ __forceinline__ void bsplit(float v, __nv_bfloat16& h, __nv_bfloat16& l) {
  h = __float2bfloat16(v);
  l = __float2bfloat16(v - __bfloat162float(h));
}
__device__ __forceinline__ u64 mk64(uint32_t lo, uint32_t hi) {
  return (u64)lo | ((u64)hi << 32);
}
// packed bf16 split of a float4 (bit-identical to 4x scalar bsplit)
__device__ __forceinline__ void bsplit4(float4 v, u64& hq, u64& lq) {
  uint32_t h01, h23, l01, l23;
  asm("cvt.rn.bf16x2.f32 %0,%1,%2;" : "=r"(h01) : "f"(v.y), "f"(v.x));
  asm("cvt.rn.bf16x2.f32 %0,%1,%2;" : "=r"(h23) : "f"(v.w), "f"(v.z));
  const float f0 = __uint_as_float(h01 << 16);
  const float f1 = __uint_as_float(h01 & 0xffff0000u);
  const float f2 = __uint_as_float(h23 << 16);
  const float f3 = __uint_as_float(h23 & 0xffff0000u);
  asm("cvt.rn.bf16x2.f32 %0,%1,%2;" : "=r"(l01) : "f"(v.y - f1), "f"(v.x - f0));
  asm("cvt.rn.bf16x2.f32 %0,%1,%2;" : "=r"(l23) : "f"(v.w - f3), "f"(v.z - f2));
  hq = mk64(h01, h23);
  lq = mk64(l01, l23);
}
// packed bf16 split of 2 floats -> two u32 (bit-identical to scalar bsplit)
__device__ __forceinline__ void bsplit2(float a, float b, uint32_t& h, uint32_t& l) {
  asm("cvt.rn.bf16x2.f32 %0,%1,%2;" : "=r"(h) : "f"(b), "f"(a));
  const float fa = __uint_as_float(h << 16);
  const float fb = __uint_as_float(h & 0xffff0000u);
  asm("cvt.rn.bf16x2.f32 %0,%1,%2;" : "=r"(l) : "f"(b - fb), "f"(a - fa));
}

// ---- packed f32x2 helpers ----
__device__ __forceinline__ u64 pk2(float lo, float hi) {
  u64 r; asm("mov.b64 %0,{%1,%2};" : "=l"(r) : "f"(lo), "f"(hi)); return r;
}
__device__ __forceinline__ u64 bc2(float v) { return pk2(v, v); }
__device__ __forceinline__ void up2(u64 v, float& lo, float& hi) {
  asm("mov.b64 {%0,%1},%2;" : "=f"(lo), "=f"(hi) : "l"(v));
}
__device__ __forceinline__ u64 fma2(u64 a, u64 b, u64 c) {
  u64 d; asm("fma.rn.f32x2 %0,%1,%2,%3;" : "=l"(d) : "l"(a), "l"(b), "l"(c)); return d;
}
__device__ __forceinline__ u64 mul2(u64 a, u64 b) {
  u64 d; asm("mul.rn.f32x2 %0,%1,%2;" : "=l"(d) : "l"(a), "l"(b)); return d;
}
__device__ __forceinline__ u64 add2(u64 a, u64 b) {
  u64 d; asm("add.rn.f32x2 %0,%1,%2;" : "=l"(d) : "l"(a), "l"(b)); return d;
}
__device__ __forceinline__ u64 neg2(u64 a) { return a ^ 0x8000000080000000ULL; }

// gram smem byte layout (total 93696):
#define OFF_XL  33792
#define OFF_KK  67584
#define OFF_WTH 84224
#define OFF_WTL 88832
#define OFF_SQ  93440
#define SMEM_BYTES 93696

// ---------------------------------------------------------------------------
// Kernel A: centering + tensor-core Gram + exp + tensor-core P=KW, Y=W^T P
// grid 4096, block 256
// ---------------------------------------------------------------------------
__global__ __launch_bounds__(256) void gram_kernel(const float* __restrict__ x,
                                                   const float* __restrict__ W) {
  extern __shared__ char smc[];
  __nv_bfloat16* Xh = (__nv_bfloat16*)smc;              // 64 x 264
  __nv_bfloat16* Xl = (__nv_bfloat16*)(smc + OFF_XL);   // 64 x 264
  float* KK  = (float*)(smc + OFF_KK);                  // 64 x 65
  __nv_bfloat16* Wth = (__nv_bfloat16*)(smc + OFF_WTH); // 32 x 72
  __nv_bfloat16* Wtl = (__nv_bfloat16*)(smc + OFF_WTL);
  float* sq  = (float*)(smc + OFF_SQ);                  // 64
  __nv_bfloat16* Kh  = (__nv_bfloat16*)smc;             // 64 x 72
  __nv_bfloat16* Kl  = (__nv_bfloat16*)(smc + 9216);    // 64 x 72
  __nv_bfloat16* Pth = (__nv_bfloat16*)(smc + OFF_XL);          // 32 x 72
  __nv_bfloat16* Ptl = (__nv_bfloat16*)(smc + OFF_XL + 4608);   // 32 x 72

  const int b    = blockIdx.x;
  const int tid  = threadIdx.x;
  const int warp = tid >> 5;
  const int lane = tid & 31;

  for (int i = tid; i < 20 * 64; i += 256) {
    const int d = i >> 6, k = i & 63;
    const float w = W[k * 20 + d];
    __nv_bfloat16 h, l;
    bsplit(w, h, l);
    Wth[d * 72 + k] = h;
    Wtl[d * 72 + k] = l;
  }

  const float* xb = x + (size_t)b * (64 * 256);
#pragma unroll
  for (int r8 = 0; r8 < 8; r8++) {
    const int r = warp * 8 + r8;
    const float4* row = (const float4*)(xb + r * 256);
    float4 v0 = row[lane];
    float4 v1 = row[lane + 32];
    float s = v0.x + v0.y + v0.z + v0.w + v1.x + v1.y + v1.z + v1.w;
    s += __shfl_xor_sync(FULL, s, 16);
    s += __shfl_xor_sync(FULL, s, 8);
    s += __shfl_xor_sync(FULL, s, 4);
    s += __shfl_xor_sync(FULL, s, 2);
    s += __shfl_xor_sync(FULL, s, 1);
    const float m = s * (1.0f / 256.0f);
    v0.x -= m; v0.y -= m; v0.z -= m; v0.w -= m;
    v1.x -= m; v1.y -= m; v1.z -= m; v1.w -= m;

    u64 hq, lq;
    bsplit4(v0, hq, lq);
    *(u64*)(Xh + r * 264 + 4 * lane) = hq;
    *(u64*)(Xl + r * 264 + 4 * lane) = lq;
    bsplit4(v1, hq, lq);
    *(u64*)(Xh + r * 264 + 128 + 4 * lane) = hq;
    *(u64*)(Xl + r * 264 + 128 + 4 * lane) = lq;
  }
  __syncthreads();

  const int mrow = lane & 7;
  const int msel = lane >> 3;
  const int cofs = (msel >> 1) * 8;
  const int rsel = (msel & 1) * 8;
  const int r0 = lane >> 2;
  const int cb = 2 * (lane & 3);

  {
    const int bj = (warp & 3) * 16;
    const int bi = (warp >> 2) * 16;
    const uint32_t LOFF = 64 * 264 * 2;

    uint32_t aA0 = s2u(Xh + (bi + rsel + mrow) * 264 + cofs);
    uint32_t aA1 = aA0 + 32 * 264 * 2;
    uint32_t aB  = s2u(Xh + (bj + rsel + mrow) * 264 + cofs);

    float c0[8], c1[8];
#pragma unroll
    for (int i = 0; i < 8; i++) { c0[i] = 0.f; c1[i] = 0.f; }

#pragma unroll 4
    for (int kc = 0; kc < 16; kc++) {
      uint32_t Ah[4], Al[4], Bh[4], Bl[4], A1h[4], A1l[4];
      ldsm4(aA0, Ah);  ldsm4(aA0 + LOFF, Al);
      ldsm4(aA1, A1h); ldsm4(aA1 + LOFF, A1l);
      ldsm4(aB, Bh);   ldsm4(aB + LOFF, Bl);

      mma16816(c0,     Ah,  Bh[0], Bh[2]);
      mma16816(c0,     Ah,  Bl[0], Bl[2]);
      mma16816(c0,     Al,  Bh[0], Bh[2]);
      mma16816(c0 + 4, Ah,  Bh[1], Bh[3]);
      mma16816(c0 + 4, Ah,  Bl[1], Bl[3]);
      mma16816(c0 + 4, Al,  Bh[1], Bh[3]);

      mma16816(c1,     A1h, Bh[0], Bh[2]);
      mma16816(c1,     A1h, Bl[0], Bl[2]);
      mma16816(c1,     A1l, Bh[0], Bh[2]);
      mma16816(c1 + 4, A1h, Bh[1], Bh[3]);
      mma16816(c1 + 4, A1h, Bl[1], Bl[3]);
      mma16816(c1 + 4, A1l, Bh[1], Bh[3]);

      aA0 += 32; aA1 += 32; aB += 32;
    }

    float* K0 = KK + (bi + r0) * 65 + bj + cb;
    K0[0] = c0[0];  K0[1] = c0[1];
    K0[8 * 65] = c0[2];  K0[8 * 65 + 1] = c0[3];
    K0[8] = c0[4];  K0[9] = c0[5];
    K0[8 * 65 + 8] = c0[6];  K0[8 * 65 + 9] = c0[7];
    float* K1 = KK + (bi + 32 + r0) * 65 + bj + cb;
    K1[0] = c1[0];  K1[1] = c1[1];
    K1[8 * 65] = c1[2];  K1[8 * 65 + 1] = c1[3];
    K1[8] = c1[4];  K1[9] = c1[5];
    K1[8 * 65 + 8] = c1[6];  K1[8 * 65 + 9] = c1[7];
  }
  __syncthreads();

  if (tid < 64) sq[tid] = KK[tid * 65 + tid];
  __syncthreads();

  // ---- K = exp(-50 * d2) -> bf16 hi/lo, d-paired packed stores ----
  for (int p = tid; p < 2048; p += 256) {
    const int c = p >> 5;
    const int d = (p & 31) * 2;
    const float g0 = KK[c * 65 + d];
    const float g1 = KK[c * 65 + d + 1];
    const float sc = sq[c];
    float d20 = fmaxf(sc + sq[d]     - 2.f * g0, 0.f) * (1.0f / 256.0f);
    float d21 = fmaxf(sc + sq[d + 1] - 2.f * g1, 0.f) * (1.0f / 256.0f);
    const float kv0 = __expf(-50.f * d20);
    const float kv1 = __expf(-50.f * d21);
    uint32_t h, l;
    bsplit2(kv0, kv1, h, l);
    *(uint32_t*)(Kh + c * 72 + d) = h;
    *(uint32_t*)(Kl + c * 72 + d) = l;
  }
  __syncthreads();

  {
    const int bi = (warp & 3) * 16;
    const int nh = (warp >> 2) * 16;

    uint32_t aA = s2u(Kh + (bi + rsel + mrow) * 72 + cofs);
    uint32_t aB = s2u(Wth + (nh + rsel + mrow) * 72 + cofs);
    const uint32_t KLO = 9216;
    const uint32_t WLO = 4608;

    float c0[8];
#pragma unroll
    for (int i = 0; i < 8; i++) c0[i] = 0.f;

#pragma unroll
    for (int kc = 0; kc < 4; kc++) {
      uint32_t Ah[4], Al[4], Bh[4], Bl[4];
      ldsm4(aA, Ah); ldsm4(aA + KLO, Al);
      ldsm4(aB, Bh); ldsm4(aB + WLO, Bl);
      mma16816(c0,     Ah, Bh[0], Bh[2]);
      mma16816(c0,     Ah, Bl[0], Bl[2]);
      mma16816(c0,     Al, Bh[0], Bh[2]);
      mma16816(c0 + 4, Ah, Bh[1], Bh[3]);
      mma16816(c0 + 4, Ah, Bl[1], Bl[3]);
      mma16816(c0 + 4, Al, Bh[1], Bh[3]);
      aA += 32; aB += 32;
    }

    const int cc0 = bi + r0;
    const int cc1 = bi + r0 + 8;
    const int dd0 = nh + cb;
    __nv_bfloat16 h, l;
#pragma unroll
    for (int i = 0; i < 8; i++) {
      const int dd = dd0 + (i & 1) + ((i >> 2) << 3);
      const int cc = (i & 2) ? cc1 : cc0;
      bsplit(c0[i], h, l);
      Pth[dd * 72 + cc] = h;
      Ptl[dd * 72 + cc] = l;
    }
  }
  __syncthreads();

  if (warp < 4) {
    const int e0 = (warp & 1) * 16;
    const int f0 = (warp >> 1) * 16;

    uint32_t aA = s2u(Wth + (e0 + rsel + mrow) * 72 + cofs);
    uint32_t aB = s2u(Pth + (f0 + rsel + mrow) * 72 + cofs);
    const uint32_t WLO = 4608;
    const uint32_t PLO = 4608;

    float c0[8];
#pragma unroll
    for (int i = 0; i < 8; i++) c0[i] = 0.f;

#pragma unroll
    for (int kc = 0; kc < 4; kc++) {
      uint32_t Ah[4], Al[4], Bh[4], Bl[4];
      ldsm4(aA, Ah); ldsm4(aA + WLO, Al);
      ldsm4(aB, Bh); ldsm4(aB + PLO, Bl);
      mma16816(c0,     Ah, Bh[0], Bh[2]);
      mma16816(c0,     Ah, Bl[0], Bl[2]);
      mma16816(c0,     Al, Bh[0], Bh[2]);
      mma16816(c0 + 4, Ah, Bh[1], Bh[3]);
      mma16816(c0 + 4, Ah, Bl[1], Bl[3]);
      mma16816(c0 + 4, Al, Bh[1], Bh[3]);
      aA += 32; aB += 32;
    }

    float* Yb = g_Y + (size_t)b * 400;
#pragma unroll
    for (int i = 0; i < 8; i++) {
      const int ee = e0 + r0 + ((i & 2) ? 8 : 0);
      const int ff = f0 + cb + (i & 1) + ((i >> 2) << 3);
      if (ee < 20 && ff < 20) Yb[ee * 20 + ff] = c0[i];
    }
  }
}

// ---------------------------------------------------------------------------
// Kernel B: packed-f32x2 warp Jacobi, TWO matrices/warp, smem-based exchange,
// fast-math angle computation (fdividef + rsqrt-sqrt).
// ---------------------------------------------------------------------------
__global__ __launch_bounds__(64, 8) void eig_kernel(const float* __restrict__ lin_w,
                                                    const float* __restrict__ lin_b,
                                                    float* __restrict__ out) {
  __shared__ __align__(16) char wsm[2][6720];

  const int warp = threadIdx.x >> 5;
  const int lane = threadIdx.x & 31;
  ulonglong2* rowbuf = (ulonglong2*)(wsm[warp]);            // [10][33]
  u64*        dgbuf  = (u64*)(wsm[warp] + 5280);            // [32]
  ulonglong2* csbuf  = (ulonglong2*)(wsm[warp] + 5536);     // [20]

  const int b0 = (blockIdx.x * 2 + warp) * 2;
  const float* Y0 = g_Y + (size_t)b0 * 400;
  const float* Y1 = Y0 + 400;

  const int rlane = (lane < 20) ? lane : 0;

  u64 a[20], u[20];
#pragma unroll
  for (int j = 0; j < 20; j++) {
    a[j] = (lane < 20) ? pk2(Y0[lane * 20 + j], Y1[lane * 20 + j]) : 0ULL;
    u[j] = (lane == j) ? bc2(1.f) : 0ULL;
  }
  u64 dg = (lane < 20) ? pk2(Y0[lane * 21], Y1[lane * 21]) : 0ULL;

  int m = (lane + 37) % 19;

  for (int sw = 0; sw < NSWEEP; sw++) {
#pragma unroll
    for (int r = 0; r < 19; r++) {
      const int C = (2 * r + 18) % 19;
      const int D = ((18 + r) % 19) + 1;
      int uu = C - lane;
      uu += (uu < 0) ? 19 : 0;
      uu += (uu < 0) ? 19 : 0;
      int t = (m == 18) ? 0 : uu + 1;
      t = (lane == 0) ? D : t;
      const bool isp = lane < t;

      // ---- publish pre-round rows + diagonal ----
#pragma unroll
      for (int mm = 0; mm < 10; mm++) {
        ulonglong2 v; v.x = a[2 * mm]; v.y = a[2 * mm + 1];
        rowbuf[mm * 33 + lane] = v;
      }
      dgbuf[lane] = dg;
      __syncwarp();

      // ---- gather: apq (symmetrized) and partner diagonal ----
      const ulonglong2 own_pair = rowbuf[(t >> 1) * 33 + lane];
      const u64 apq_own = (t & 1) ? own_pair.y : own_pair.x;
      const ulonglong2 oth_pair = rowbuf[(rlane >> 1) * 33 + t];
      const u64 apq_oth = (rlane & 1) ? oth_pair.y : oth_pair.x;
      const u64 apq = mul2(bc2(0.5f), add2(apq_own, apq_oth));
      const u64 att = dgbuf[t];

      // ---- fast angles (identical bits on both pair lanes) ----
      float apqx, apqy, dgx, dgy, atx, aty;
      up2(apq, apqx, apqy);
      up2(dg, dgx, dgy);
      up2(att, atx, aty);
      float cx, sx, tgx, cy, sy, tgy;
      {
        const float app = isp ? dgx : atx;
        const float aqq = isp ? atx : dgx;
        const float tau = __fdividef((aqq - app) * 0.5f, apqx);
        const float s1  = fmaf(tau, tau, 1.f);
        const float tt  = __fdividef(copysignf(1.f, tau),
                                     fabsf(tau) + s1 * rsqrtf(s1));
        const float cc  = rsqrtf(fmaf(tt, tt, 1.f));
        const bool ok = (fabsf(apqx) > 1e-20f) && (lane < 20);
        cx  = ok ? cc : 1.f;
        sx  = ok ? tt * cc : 0.f;
        tgx = ok ? tt : 0.f;
      }
      {
        const float app = isp ? dgy : aty;
        const float aqq = isp ? aty : dgy;
        const float tau = __fdividef((aqq - app) * 0.5f, apqy);
        const float s1  = fmaf(tau, tau, 1.f);
        const float tt  = __fdividef(copysignf(1.f, tau),
                                     fabsf(tau) + s1 * rsqrtf(s1));
        const float cc  = rsqrtf(fmaf(tt, tt, 1.f));
        const bool ok = (fabsf(apqy) > 1e-20f) && (lane < 20);
        cy  = ok ? cc : 1.f;
        sy  = ok ? tt * cc : 0.f;
        tgy = ok ? tt : 0.f;
      }
      const u64 c  = pk2(cx, cy);
      const u64 s  = pk2(sx, sy);
      const u64 tg = pk2(tgx, tgy);

      dg = fma2(isp ? neg2(tg) : tg, apq, dg);

      // ---- pair leader publishes (c,s) for col phase ----
      if (isp) { ulonglong2 cs; cs.x = c; cs.y = s; csbuf[lane] = cs; }

      // ---- row phase: read partner's pre-round row from smem ----
      {
        const u64 se = isp ? neg2(s) : s;
#pragma unroll
        for (int mm = 0; mm < 10; mm++) {
          const ulonglong2 rt = rowbuf[mm * 33 + t];
          a[2 * mm]     = fma2(se, rt.x, mul2(c, a[2 * mm]));
          a[2 * mm + 1] = fma2(se, rt.y, mul2(c, a[2 * mm + 1]));
        }
      }
      __syncwarp();

      // ---- col phase ----
#pragma unroll
      for (int k = 0; k < 10; k++) {
        const int u0 = (k == 0) ? 0 : ((k - 1 + r) % 19) + 1;
        const int v0 = ((18 - k + r) % 19) + 1;
        const int pk = u0 < v0 ? u0 : v0;
        const int qk = u0 < v0 ? v0 : u0;
        const ulonglong2 cs = csbuf[pk];
        const u64 ck  = cs.x;
        const u64 sk  = cs.y;
        const u64 nsk = neg2(sk);
        const u64 ap = a[pk], aq = a[qk];
        a[pk] = fma2(nsk, aq, mul2(ck, ap));
        a[qk] = fma2(sk,  ap, mul2(ck, aq));
        const u64 up = u[pk], uq = u[qk];
        u[pk] = fma2(nsk, uq, mul2(ck, up));
        u[qk] = fma2(sk,  up, mul2(ck, uq));
      }

      m = (m == 0) ? 18 : m - 1;
    }
  }

  // ---- eigenvalues from converged diagonal of a[] ----
  u64 lam = 0ULL;
#pragma unroll
  for (int j = 0; j < 20; j++) lam = (lane == j) ? a[j] : lam;
  float lamx, lamy;
  up2(lam, lamx, lamy);
  const u64 lg_pk = pk2(__logf(fmaxf(lamx, 1e-4f)), __logf(fmaxf(lamy, 1e-4f)));

  // ---- overlay tail buffers on Jacobi buffers ----
  __syncwarp();
  u64* sW = (u64*)(wsm[warp]);           // [420] 20x21 packed
  u64* sU = (u64*)(wsm[warp] + 3360);    // [420]

#pragma unroll
  for (int j = 0; j < 20; j++) {
    const u64 lgj = __shfl_sync(FULL, lg_pk, j);
    if (lane < 20) {
      sW[lane * 21 + j] = mul2(u[j], lgj);
      sU[lane * 21 + j] = u[j];
    }
  }
  __syncwarp();

  u64 accv[10];
#pragma unroll
  for (int h = 0; h < 10; h++) accv[h] = 0ULL;

  for (int t = lane; t < 210; t += 32) {
    int i = (int)((41.0f - sqrtf(fmaf(-8.f, (float)t, 1681.0f))) * 0.5f);
    int st = 20 * i - ((i * (i - 1)) >> 1);
    if (st > t) { i--; st = 20 * i - ((i * (i - 1)) >> 1); }
    else if (t >= st + (20 - i)) { st += 20 - i; i++; }
    const int k = i + (t - st);
    u64 mm = 0ULL;
#pragma unroll
    for (int j = 0; j < 20; j++)
      mm = fma2(sW[i * 21 + j], sU[k * 21 + j], mm);
#pragma unroll
    for (int h = 0; h < 10; h++)
      accv[h] = fma2(mm, bc2(lin_w[h * 210 + t]), accv[h]);
  }
#pragma unroll
  for (int h = 0; h < 10; h++) {
    u64 v = accv[h];
    v = add2(v, __shfl_xor_sync(FULL, v, 16));
    v = add2(v, __shfl_xor_sync(FULL, v, 8));
    v = add2(v, __shfl_xor_sync(FULL, v, 4));
    v = add2(v, __shfl_xor_sync(FULL, v, 2));
    v = add2(v, __shfl_xor_sync(FULL, v, 1));
    accv[h] = v;
  }
  if (lane == 0) {
#pragma unroll
    for (int h = 0; h < 10; h++) {
      float vx, vy;
      up2(accv[h], vx, vy);
      const float bb = lin_b[h];
      out[b0 * 10 + h]      = vx + bb;
      out[b0 * 10 + 10 + h] = vy + bb;
    }
  }
}

// ---------------------------------------------------------------------------
extern "C" void kernel_launch(void* const* d_in, const int* in_sizes, int n_in,
                              void* d_out, int out_size) {
  const float* x  = (const float*)d_in[0];
  const float* W  = (const float*)d_in[1];
  const float* lw = (const float*)d_in[2];
  const float* lb = (const float*)d_in[3];
  float* out = (float*)d_out;

  cudaFuncSetAttribute(gram_kernel, cudaFuncAttributeMaxDynamicSharedMemorySize,
                       SMEM_BYTES);

  gram_kernel<<<4096, 256, SMEM_BYTES>>>(x, W);
  eig_kernel<<<1024, 64>>>(lw, lb, out);
}